// round 1
// baseline (speedup 1.0000x reference)
#include <cuda_runtime.h>
#include <math.h>

#define B_      16384
#define K_      32
#define LATENT_ 256
#define ACT_    64
#define H_      128
#define Q_      65536
#define EPS_    0.01f

// Scratch (allowed: __device__ globals, not runtime allocation)
__device__ float g_emb_a[B_ * H_];
__device__ float g_emb_l[B_ * H_];
__device__ float g_negemb[Q_ * H_];

__device__ __forceinline__ float san(float x) { return isfinite(x) ? x : 0.0f; }

// ---------------------------------------------------------------------------
// Fused 2-layer MLP: out = relu(X @ w1 + b1) @ w2 + b2, sanitized.
// Block: 64 rows x 128 (=H) cols. 256 threads, each owns a 4x8 micro-tile.
// Hidden activations live only in shared memory.
// dst selects which __device__ scratch buffer receives the output.
// ---------------------------------------------------------------------------
__device__ __forceinline__ float* dst_of(int which) {
    return which == 0 ? g_emb_a : (which == 1 ? g_emb_l : g_negemb);
}

template <int KIN>
__global__ __launch_bounds__(256) void mlp_kernel(
    const float* __restrict__ X,
    const float* __restrict__ w1, const float* __restrict__ b1,
    const float* __restrict__ w2, const float* __restrict__ b2,
    int which)
{
    extern __shared__ float sm[];
    float* Xs  = sm;                 // [64][33]
    float* Ws  = sm + 64 * 33;       // [32][128]
    float* hid = Ws + 32 * 128;      // [64][132]

    float* __restrict__ out = dst_of(which);

    const int tid = threadIdx.x;
    const int tx  = tid & 15;        // col group: cols tx + 16*i
    const int ty  = tid >> 4;        // row group: rows ty + 16*m
    const int rowBase = blockIdx.x * 64;

    float acc[4][8];
#pragma unroll
    for (int m = 0; m < 4; m++)
#pragma unroll
        for (int i = 0; i < 8; i++) acc[m][i] = 0.0f;

    // ---- Layer 1: hid = relu(X @ w1 + b1) ----
    for (int k0 = 0; k0 < KIN; k0 += 32) {
#pragma unroll
        for (int p = 0; p < 8; p++) {            // 64x32 X tile
            int idx = tid + p * 256;
            int r = idx >> 5, c = idx & 31;
            Xs[r * 33 + c] = san(X[(rowBase + r) * KIN + k0 + c]);
        }
#pragma unroll
        for (int p = 0; p < 16; p++) {           // 32x128 W1 tile
            int idx = tid + p * 256;
            int c = idx & 127, r = idx >> 7;
            Ws[r * 128 + c] = w1[(k0 + r) * H_ + c];
        }
        __syncthreads();
#pragma unroll
        for (int kk = 0; kk < 32; kk++) {
            float xv[4];
#pragma unroll
            for (int m = 0; m < 4; m++) xv[m] = Xs[(ty + 16 * m) * 33 + kk];
#pragma unroll
            for (int i = 0; i < 8; i++) {
                float wv = Ws[kk * 128 + tx + 16 * i];
#pragma unroll
                for (int m = 0; m < 4; m++) acc[m][i] += xv[m] * wv;
            }
        }
        __syncthreads();
    }

#pragma unroll
    for (int i = 0; i < 8; i++) {
        float bias = b1[tx + 16 * i];
#pragma unroll
        for (int m = 0; m < 4; m++) {
            float v = acc[m][i] + bias;
            hid[(ty + 16 * m) * 132 + tx + 16 * i] = v > 0.0f ? v : 0.0f;
            acc[m][i] = 0.0f;
        }
    }
    __syncthreads();

    // ---- Layer 2: out = hid @ w2 + b2 ----
    for (int k0 = 0; k0 < H_; k0 += 32) {
#pragma unroll
        for (int p = 0; p < 16; p++) {           // 32x128 W2 tile
            int idx = tid + p * 256;
            int c = idx & 127, r = idx >> 7;
            Ws[r * 128 + c] = w2[(k0 + r) * H_ + c];
        }
        __syncthreads();
#pragma unroll
        for (int kk = 0; kk < 32; kk++) {
            float xv[4];
#pragma unroll
            for (int m = 0; m < 4; m++) xv[m] = hid[(ty + 16 * m) * 132 + k0 + kk];
#pragma unroll
            for (int i = 0; i < 8; i++) {
                float wv = Ws[kk * 128 + tx + 16 * i];
#pragma unroll
                for (int m = 0; m < 4; m++) acc[m][i] += xv[m] * wv;
            }
        }
        __syncthreads();
    }

#pragma unroll
    for (int i = 0; i < 8; i++) {
        float bias = b2[tx + 16 * i];
#pragma unroll
        for (int m = 0; m < 4; m++) {
            out[(rowBase + ty + 16 * m) * H_ + tx + 16 * i] = san(acc[m][i] + bias);
        }
    }
}

// ---------------------------------------------------------------------------
// Loss: one warp per sample b.
// logits[0] = emb_a[b].emb_l[b]/t ; logits[1+k] = emb_a[b].negemb[idx[b,k]]/t
// clip/sanitize, log-softmax over 33, label-smoothed CE, out = -clip(loss).
// ---------------------------------------------------------------------------
__global__ __launch_bounds__(256) void loss_kernel(
    const int* __restrict__ neg_idx,
    const float* __restrict__ temp_ptr,
    float* __restrict__ out)
{
    const int warp = threadIdx.x >> 5;
    const int lane = threadIdx.x & 31;
    const int b = blockIdx.x * 8 + warp;

    float t = *temp_ptr;
    if (!isfinite(t)) t = 0.1f;
    t = fminf(fmaxf(t, 0.01f), 10.0f);
    const float invt = 1.0f / t;

    const float4 a = reinterpret_cast<const float4*>(g_emb_a + (size_t)b * H_)[lane];
    const int my_idx = neg_idx[b * K_ + lane];

    // positive logit
    float4 v = reinterpret_cast<const float4*>(g_emb_l + (size_t)b * H_)[lane];
    float s = a.x * v.x + a.y * v.y + a.z * v.z + a.w * v.w;
#pragma unroll
    for (int o = 16; o > 0; o >>= 1) s += __shfl_xor_sync(0xffffffffu, s, o);
    float pos = s;

    // 32 negative logits; lane k keeps logit for negative k
    float myneg = 0.0f;
    for (int k = 0; k < K_; k++) {
        int row = __shfl_sync(0xffffffffu, my_idx, k);
        float4 nv = reinterpret_cast<const float4*>(g_negemb + (size_t)row * H_)[lane];
        float d = a.x * nv.x + a.y * nv.y + a.z * nv.z + a.w * nv.w;
#pragma unroll
        for (int o = 16; o > 0; o >>= 1) d += __shfl_xor_sync(0xffffffffu, d, o);
        if (lane == k) myneg = d;
    }

    // scale by 1/t, sanitize, clip to [-20, 20]
    pos *= invt;
    if (!isfinite(pos)) pos = 0.0f;
    pos = fminf(fmaxf(pos, -20.0f), 20.0f);
    myneg *= invt;
    if (!isfinite(myneg)) myneg = 0.0f;
    myneg = fminf(fmaxf(myneg, -20.0f), 20.0f);

    // log-softmax over 33 logits (lane l holds logit_{l+1}; logit_0 = pos)
    float m = myneg;
#pragma unroll
    for (int o = 16; o > 0; o >>= 1) m = fmaxf(m, __shfl_xor_sync(0xffffffffu, m, o));
    m = fmaxf(m, pos);

    float se = expf(myneg - m);
    float sl = myneg;
#pragma unroll
    for (int o = 16; o > 0; o >>= 1) {
        se += __shfl_xor_sync(0xffffffffu, se, o);
        sl += __shfl_xor_sync(0xffffffffu, sl, o);
    }
    se += expf(pos - m);
    sl += pos;

    float lse = m + logf(se);
    float logp0 = pos - lse;
    float meanlogp = sl * (1.0f / 33.0f) - lse;

    float loss = -(1.0f - EPS_) * logp0 - EPS_ * meanlogp;
    if (!isfinite(loss)) loss = 0.0f;
    loss = fminf(fmaxf(loss, -10.0f), 10.0f);

    if (lane == 0) out[b] = -loss;
}

// ---------------------------------------------------------------------------
extern "C" void kernel_launch(void* const* d_in, const int* in_sizes, int n_in,
                              void* d_out, int out_size)
{
    const float* action  = (const float*)d_in[0];
    const float* latent  = (const float*)d_in[1];
    const float* queue   = (const float*)d_in[2];
    const int*   neg_idx = (const int*)  d_in[3];
    const float* a_w1 = (const float*)d_in[4];
    const float* a_b1 = (const float*)d_in[5];
    const float* a_w2 = (const float*)d_in[6];
    const float* a_b2 = (const float*)d_in[7];
    const float* l_w1 = (const float*)d_in[8];
    const float* l_b1 = (const float*)d_in[9];
    const float* l_w2 = (const float*)d_in[10];
    const float* l_b2 = (const float*)d_in[11];
    const float* temp = (const float*)d_in[12];
    float* out = (float*)d_out;

    const int SMEM = (64 * 33 + 32 * 128 + 64 * 132) * 4;  // 58624 bytes

    cudaFuncSetAttribute((const void*)mlp_kernel<ACT_>,
                         cudaFuncAttributeMaxDynamicSharedMemorySize, SMEM);
    cudaFuncSetAttribute((const void*)mlp_kernel<LATENT_>,
                         cudaFuncAttributeMaxDynamicSharedMemorySize, SMEM);

    // emb_a = mlp_a(action)            [16384,128]
    mlp_kernel<ACT_><<<B_ / 64, 256, SMEM>>>(action, a_w1, a_b1, a_w2, a_b2, 0);
    // emb_l = mlp_l(latent)            [16384,128]
    mlp_kernel<LATENT_><<<B_ / 64, 256, SMEM>>>(latent, l_w1, l_b1, l_w2, l_b2, 1);
    // negemb = mlp_l(queue)            [65536,128]  (dedup: Q rows, not B*K)
    mlp_kernel<LATENT_><<<Q_ / 64, 256, SMEM>>>(queue, l_w1, l_b1, l_w2, l_b2, 2);
    // gather + logits + log-softmax + smoothed CE
    loss_kernel<<<B_ / 8, 256>>>(neg_idx, temp, out);
}

// round 3
// speedup vs baseline: 2.2610x; 2.2610x over previous
#include <cuda_runtime.h>
#include <cuda_bf16.h>
#include <math.h>
#include <stdint.h>

#define B_      16384
#define K_      32
#define LATENT_ 256
#define ACT_    64
#define H_      128
#define Q_      65536
#define EPS_    0.01f

// ---------------- scratch (device globals; no runtime alloc) ----------------
__device__ __nv_bfloat16 g_emb_a[B_ * H_];
__device__ __nv_bfloat16 g_emb_l[B_ * H_];
__device__ __nv_bfloat16 g_negemb[Q_ * H_];
__device__ __nv_bfloat16 g_aw1t[H_ * ACT_];     // [H][ACT]    = a_w1^T
__device__ __nv_bfloat16 g_aw2t[H_ * H_];       // [H][H]      = a_w2^T
__device__ __nv_bfloat16 g_lw1t[H_ * LATENT_];  // [H][LATENT] = l_w1^T
__device__ __nv_bfloat16 g_lw2t[H_ * H_];       // [H][H]      = l_w2^T

__device__ __forceinline__ float san(float x) { return isfinite(x) ? x : 0.0f; }

__device__ __forceinline__ uint32_t smem_u32(const void* p) {
    uint32_t a;
    asm("{ .reg .u64 t; cvta.to.shared.u64 t, %1; cvt.u32.u64 %0, t; }" : "=r"(a) : "l"(p));
    return a;
}
__device__ __forceinline__ uint32_t pack_bf16x2(float lo, float hi) {
    uint32_t r;
    asm("cvt.rn.bf16x2.f32 %0, %1, %2;" : "=r"(r) : "f"(hi), "f"(lo));
    return r;
}
__device__ __forceinline__ void ldsm4(uint32_t* r, uint32_t addr) {
    asm volatile("ldmatrix.sync.aligned.m8n8.x4.shared.b16 {%0,%1,%2,%3}, [%4];"
                 : "=r"(r[0]), "=r"(r[1]), "=r"(r[2]), "=r"(r[3]) : "r"(addr));
}
__device__ __forceinline__ void mma16816(float* d, const uint32_t* a, const uint32_t* b) {
    asm volatile(
        "mma.sync.aligned.m16n8k16.row.col.f32.bf16.bf16.f32 "
        "{%0,%1,%2,%3}, {%4,%5,%6,%7}, {%8,%9}, {%0,%1,%2,%3};"
        : "+f"(d[0]), "+f"(d[1]), "+f"(d[2]), "+f"(d[3])
        : "r"(a[0]), "r"(a[1]), "r"(a[2]), "r"(a[3]), "r"(b[0]), "r"(b[1]));
}

// ---------------------------------------------------------------------------
// Weight transpose + bf16 convert (tiny, once per launch)
// ---------------------------------------------------------------------------
__global__ void prep_weights(const float* __restrict__ aw1, const float* __restrict__ aw2,
                             const float* __restrict__ lw1, const float* __restrict__ lw2)
{
    int i = blockIdx.x * blockDim.x + threadIdx.x;
    if (i < H_ * ACT_) {
        int n = i / ACT_, k = i % ACT_;
        g_aw1t[i] = __float2bfloat16(aw1[k * H_ + n]);
    }
    int i2 = i - H_ * ACT_;
    if (i2 >= 0 && i2 < H_ * H_) {
        int n = i2 / H_, k = i2 % H_;
        g_aw2t[i2] = __float2bfloat16(aw2[k * H_ + n]);
    }
    int i3 = i2 - H_ * H_;
    if (i3 >= 0 && i3 < H_ * LATENT_) {
        int n = i3 / LATENT_, k = i3 % LATENT_;
        g_lw1t[i3] = __float2bfloat16(lw1[k * H_ + n]);
    }
    int i4 = i3 - H_ * H_;
    if (i4 >= 0 && i4 < H_ * H_) {
        int n = i4 / H_, k = i4 % H_;
        g_lw2t[i4] = __float2bfloat16(lw2[k * H_ + n]);
    }
}

// ---------------------------------------------------------------------------
// Fused 2-layer MLP via mma.sync (baseline ISA, works at compute_103):
//   tile: 128 rows x 128 cols per CTA, 8 warps in 4x2 grid (warp = 32x64)
//   layer1: D1 = X @ W1 (A: Xs [128][KIN] bf16, B: W1T [128][KIN] bf16)
//   hidden = relu(D1 + b1) -> smem ; layer2: D2 = hidden @ W2
//   out = san(D2 + b2) -> bf16 gmem
// ---------------------------------------------------------------------------
template <int KIN>
__global__ __launch_bounds__(256, 1) void mlp_mma(
    const float* __restrict__ X,
    const float* __restrict__ b1g, const float* __restrict__ b2g, int which)
{
    constexpr int PAD  = 8;                    // halves
    constexpr int S1   = KIN + PAD;            // Xs/Ws1 row stride (halves)
    constexpr int SH   = H_ + PAD;             // Hs/Ws2 row stride (halves)
    constexpr int R1B  = (128 * S1 * 2 > 128 * SH * 2) ? 128 * S1 * 2 : 128 * SH * 2;
    constexpr int R2B  = R1B;

    extern __shared__ __align__(16) char smem[];
    char* r1 = smem;                 // Xs -> Hs -> out-stage
    char* r2 = smem + R1B;           // W1T -> W2T
    float* b1s = (float*)(smem + R1B + R2B);
    float* b2s = b1s + 128;

    const uint32_t sb1 = smem_u32(r1);
    const uint32_t sb2 = smem_u32(r2);

    const int tid  = threadIdx.x;
    const int wid  = tid >> 5;
    const int lane = tid & 31;
    const int rowBase = blockIdx.x * 128;
    const int wr0 = (wid >> 1) * 32;           // warp row base in tile
    const int wc0 = (wid & 1) * 64;            // warp col base in tile

    // per-lane ldmatrix offsets
    const int a_row = (lane & 7) + ((lane >> 3) & 1) * 8;
    const int a_k   = (lane >> 4) * 8;
    const int b_n   = (lane & 7) + ((lane >> 4) & 1) * 8;
    const int b_k   = ((lane >> 3) & 1) * 8;

    const __nv_bfloat16* w1t = (which == 0) ? g_aw1t : g_lw1t;
    const __nv_bfloat16* w2t = (which == 0) ? g_aw2t : g_lw2t;
    __nv_bfloat16* out = (which == 0) ? g_emb_a : ((which == 1) ? g_emb_l : g_negemb);

    if (tid < 128) { b1s[tid] = b1g[tid]; b2s[tid] = b2g[tid]; }

    // ---- stage Xs (fp32 -> san -> bf16) and W1T ----
    {
        constexpr int FQ = KIN / 4;
        for (int i = tid; i < 128 * FQ; i += 256) {
            int r = i / FQ, c = (i % FQ) * 4;
            float4 v = *(const float4*)(X + (size_t)(rowBase + r) * KIN + c);
            uint2 u;
            u.x = pack_bf16x2(san(v.x), san(v.y));
            u.y = pack_bf16x2(san(v.z), san(v.w));
            *(uint2*)(r1 + (r * S1 + c) * 2) = u;
        }
        for (int i = tid; i < 128 * FQ; i += 256) {
            int r = i / FQ, c = (i % FQ) * 4;
            *(uint2*)(r2 + (r * S1 + c) * 2) = *(const uint2*)(w1t + r * KIN + c);
        }
    }
    __syncthreads();

    // ---- layer 1 mma ----
    float acc[2][8][4];
#pragma unroll
    for (int mi = 0; mi < 2; mi++)
#pragma unroll
        for (int ni = 0; ni < 8; ni++)
#pragma unroll
            for (int q = 0; q < 4; q++) acc[mi][ni][q] = 0.0f;

    {
        uint32_t aaddr[2], baddr[4];
#pragma unroll
        for (int mi = 0; mi < 2; mi++)
            aaddr[mi] = sb1 + ((wr0 + mi * 16 + a_row) * S1 + a_k) * 2;
#pragma unroll
        for (int bi = 0; bi < 4; bi++)
            baddr[bi] = sb2 + ((wc0 + bi * 16 + b_n) * S1 + b_k) * 2;

#pragma unroll
        for (int ks = 0; ks < KIN / 16; ks++) {
            uint32_t a[2][4], b[8][2];
#pragma unroll
            for (int mi = 0; mi < 2; mi++) ldsm4(a[mi], aaddr[mi] + ks * 32);
#pragma unroll
            for (int bi = 0; bi < 4; bi++) {
                uint32_t t[4];
                ldsm4(t, baddr[bi] + ks * 32);
                b[bi * 2][0] = t[0]; b[bi * 2][1] = t[1];
                b[bi * 2 + 1][0] = t[2]; b[bi * 2 + 1][1] = t[3];
            }
#pragma unroll
            for (int mi = 0; mi < 2; mi++)
#pragma unroll
                for (int ni = 0; ni < 8; ni++) mma16816(acc[mi][ni], a[mi], b[ni]);
        }
    }
    __syncthreads();   // all reads of Xs/Ws1 done

    // ---- epilogue 1: hidden = relu(acc + b1) -> r1 ; also stage W2T -> r2 ----
    {
        const int tr = lane >> 2, tc = (lane & 3) * 2;
#pragma unroll
        for (int mi = 0; mi < 2; mi++)
#pragma unroll
            for (int ni = 0; ni < 8; ni++) {
                int col = wc0 + ni * 8 + tc;
                float bb0 = b1s[col], bb1 = b1s[col + 1];
                int row0 = wr0 + mi * 16 + tr;
                *(uint32_t*)(r1 + (row0 * SH + col) * 2) =
                    pack_bf16x2(fmaxf(acc[mi][ni][0] + bb0, 0.0f),
                                fmaxf(acc[mi][ni][1] + bb1, 0.0f));
                *(uint32_t*)(r1 + ((row0 + 8) * SH + col) * 2) =
                    pack_bf16x2(fmaxf(acc[mi][ni][2] + bb0, 0.0f),
                                fmaxf(acc[mi][ni][3] + bb1, 0.0f));
            }
        for (int i = tid; i < 128 * 32; i += 256) {
            int r = i / 32, c = (i % 32) * 4;
            *(uint2*)(r2 + (r * SH + c) * 2) = *(const uint2*)(w2t + r * H_ + c);
        }
    }
    __syncthreads();

    // ---- layer 2 mma ----
#pragma unroll
    for (int mi = 0; mi < 2; mi++)
#pragma unroll
        for (int ni = 0; ni < 8; ni++)
#pragma unroll
            for (int q = 0; q < 4; q++) acc[mi][ni][q] = 0.0f;

    {
        uint32_t aaddr[2], baddr[4];
#pragma unroll
        for (int mi = 0; mi < 2; mi++)
            aaddr[mi] = sb1 + ((wr0 + mi * 16 + a_row) * SH + a_k) * 2;
#pragma unroll
        for (int bi = 0; bi < 4; bi++)
            baddr[bi] = sb2 + ((wc0 + bi * 16 + b_n) * SH + b_k) * 2;

#pragma unroll
        for (int ks = 0; ks < H_ / 16; ks++) {
            uint32_t a[2][4], b[8][2];
#pragma unroll
            for (int mi = 0; mi < 2; mi++) ldsm4(a[mi], aaddr[mi] + ks * 32);
#pragma unroll
            for (int bi = 0; bi < 4; bi++) {
                uint32_t t[4];
                ldsm4(t, baddr[bi] + ks * 32);
                b[bi * 2][0] = t[0]; b[bi * 2][1] = t[1];
                b[bi * 2 + 1][0] = t[2]; b[bi * 2 + 1][1] = t[3];
            }
#pragma unroll
            for (int mi = 0; mi < 2; mi++)
#pragma unroll
                for (int ni = 0; ni < 8; ni++) mma16816(acc[mi][ni], a[mi], b[ni]);
        }
    }
    __syncthreads();   // all reads of Hs/Ws2 done

    // ---- epilogue 2: out = san(acc + b2) -> stage bf16 [128][128] in r1 ----
    {
        const int tr = lane >> 2, tc = (lane & 3) * 2;
#pragma unroll
        for (int mi = 0; mi < 2; mi++)
#pragma unroll
            for (int ni = 0; ni < 8; ni++) {
                int col = wc0 + ni * 8 + tc;
                float bb0 = b2s[col], bb1 = b2s[col + 1];
                int row0 = wr0 + mi * 16 + tr;
                *(uint32_t*)(r1 + (row0 * 128 + col) * 2) =
                    pack_bf16x2(san(acc[mi][ni][0] + bb0), san(acc[mi][ni][1] + bb1));
                *(uint32_t*)(r1 + ((row0 + 8) * 128 + col) * 2) =
                    pack_bf16x2(san(acc[mi][ni][2] + bb0), san(acc[mi][ni][3] + bb1));
            }
    }
    __syncthreads();
    {
        uint4* dst = (uint4*)(out + (size_t)rowBase * H_);
        const uint4* src = (const uint4*)r1;
        for (int i = tid; i < 2048; i += 256) dst[i] = src[i];
    }
}

// ---------------------------------------------------------------------------
// Loss: one warp per sample. bf16 embeddings (4 per lane -> 128 dims).
// ---------------------------------------------------------------------------
__device__ __forceinline__ float2 bf2(uint32_t u) {
    return __bfloat1622float2(*reinterpret_cast<__nv_bfloat162*>(&u));
}

__global__ __launch_bounds__(256) void loss_kernel(
    const int* __restrict__ neg_idx,
    const float* __restrict__ temp_ptr,
    float* __restrict__ out)
{
    const int warp = threadIdx.x >> 5;
    const int lane = threadIdx.x & 31;
    const int b = blockIdx.x * 8 + warp;

    float t = *temp_ptr;
    if (!isfinite(t)) t = 0.1f;
    t = fminf(fmaxf(t, 0.01f), 10.0f);
    const float invt = 1.0f / t;

    uint2 au = *(const uint2*)(g_emb_a + (size_t)b * H_ + lane * 4);
    float2 a01 = bf2(au.x), a23 = bf2(au.y);
    const int my_idx = neg_idx[b * K_ + lane];

    uint2 lu = *(const uint2*)(g_emb_l + (size_t)b * H_ + lane * 4);
    float2 l01 = bf2(lu.x), l23 = bf2(lu.y);
    float s = a01.x * l01.x + a01.y * l01.y + a23.x * l23.x + a23.y * l23.y;
#pragma unroll
    for (int o = 16; o > 0; o >>= 1) s += __shfl_xor_sync(0xffffffffu, s, o);
    float pos = s;

    float myneg = 0.0f;
    for (int k = 0; k < K_; k++) {
        int row = __shfl_sync(0xffffffffu, my_idx, k);
        uint2 nu = *(const uint2*)(g_negemb + (size_t)row * H_ + lane * 4);
        float2 n01 = bf2(nu.x), n23 = bf2(nu.y);
        float d = a01.x * n01.x + a01.y * n01.y + a23.x * n23.x + a23.y * n23.y;
#pragma unroll
        for (int o = 16; o > 0; o >>= 1) d += __shfl_xor_sync(0xffffffffu, d, o);
        if (lane == k) myneg = d;
    }

    pos *= invt;
    if (!isfinite(pos)) pos = 0.0f;
    pos = fminf(fmaxf(pos, -20.0f), 20.0f);
    myneg *= invt;
    if (!isfinite(myneg)) myneg = 0.0f;
    myneg = fminf(fmaxf(myneg, -20.0f), 20.0f);

    float m = myneg;
#pragma unroll
    for (int o = 16; o > 0; o >>= 1) m = fmaxf(m, __shfl_xor_sync(0xffffffffu, m, o));
    m = fmaxf(m, pos);

    float se = expf(myneg - m);
    float sl = myneg;
#pragma unroll
    for (int o = 16; o > 0; o >>= 1) {
        se += __shfl_xor_sync(0xffffffffu, se, o);
        sl += __shfl_xor_sync(0xffffffffu, sl, o);
    }
    se += expf(pos - m);
    sl += pos;

    float lse = m + logf(se);
    float logp0 = pos - lse;
    float meanlogp = sl * (1.0f / 33.0f) - lse;

    float loss = -(1.0f - EPS_) * logp0 - EPS_ * meanlogp;
    if (!isfinite(loss)) loss = 0.0f;
    loss = fminf(fmaxf(loss, -10.0f), 10.0f);

    if (lane == 0) out[b] = -loss;
}

// ---------------------------------------------------------------------------
extern "C" void kernel_launch(void* const* d_in, const int* in_sizes, int n_in,
                              void* d_out, int out_size)
{
    const float* action  = (const float*)d_in[0];
    const float* latent  = (const float*)d_in[1];
    const float* queue   = (const float*)d_in[2];
    const int*   neg_idx = (const int*)  d_in[3];
    const float* a_w1 = (const float*)d_in[4];
    const float* a_b1 = (const float*)d_in[5];
    const float* a_w2 = (const float*)d_in[6];
    const float* a_b2 = (const float*)d_in[7];
    const float* l_w1 = (const float*)d_in[8];
    const float* l_b1 = (const float*)d_in[9];
    const float* l_w2 = (const float*)d_in[10];
    const float* l_b2 = (const float*)d_in[11];
    const float* temp = (const float*)d_in[12];
    float* out = (float*)d_out;

    // smem sizes: 2 regions (max of operand tile / hidden tile) + bias
    auto rbytes = [](int kin) {
        int a = 128 * (kin + 8) * 2, b = 128 * (H_ + 8) * 2;
        return (a > b ? a : b);
    };
    const int SM64  = 2 * rbytes(ACT_)    + 1024;   // 2*34816 + 1024 = 70656
    const int SM256 = 2 * rbytes(LATENT_) + 1024;   // 2*67584 + 1024 = 136192

    cudaFuncSetAttribute((const void*)mlp_mma<ACT_>,
                         cudaFuncAttributeMaxDynamicSharedMemorySize, SM64);
    cudaFuncSetAttribute((const void*)mlp_mma<LATENT_>,
                         cudaFuncAttributeMaxDynamicSharedMemorySize, SM256);

    prep_weights<<<(H_ * ACT_ + H_ * H_ + H_ * LATENT_ + H_ * H_ + 255) / 256, 256>>>(
        a_w1, a_w2, l_w1, l_w2);

    mlp_mma<ACT_><<<B_ / 128, 256, SM64>>>(action, a_b1, a_b2, 0);
    mlp_mma<LATENT_><<<B_ / 128, 256, SM256>>>(latent, l_b1, l_b2, 1);
    mlp_mma<LATENT_><<<Q_ / 128, 256, SM256>>>(queue, l_b1, l_b2, 2);

    loss_kernel<<<B_ / 8, 256>>>(neg_idx, temp, out);
}

// round 5
// speedup vs baseline: 3.8797x; 1.7159x over previous
#include <cuda_runtime.h>
#include <cuda_bf16.h>
#include <math.h>
#include <stdint.h>

#define B_      16384
#define K_      32
#define LATENT_ 256
#define ACT_    64
#define H_      128
#define Q_      65536
#define EPS_    0.01f

// ---------------- scratch (device globals; no runtime alloc) ----------------
__device__ __nv_bfloat16 g_emb_a[B_ * H_];
__device__ __nv_bfloat16 g_emb_l[B_ * H_];
__device__ __nv_bfloat16 g_negemb[Q_ * H_];
__device__ __nv_bfloat16 g_aw1t[H_ * ACT_];     // [H][ACT]    = a_w1^T
__device__ __nv_bfloat16 g_aw2t[H_ * H_];       // [H][H]      = a_w2^T
__device__ __nv_bfloat16 g_lw1t[H_ * LATENT_];  // [H][LATENT] = l_w1^T
__device__ __nv_bfloat16 g_lw2t[H_ * H_];       // [H][H]      = l_w2^T

__device__ __forceinline__ float san(float x) { return isfinite(x) ? x : 0.0f; }

__device__ __forceinline__ uint32_t smem_u32(const void* p) {
    uint32_t a;
    asm("{ .reg .u64 t; cvta.to.shared.u64 t, %1; cvt.u32.u64 %0, t; }" : "=r"(a) : "l"(p));
    return a;
}
__device__ __forceinline__ uint32_t pack_bf16x2(float lo, float hi) {
    uint32_t r;
    asm("cvt.rn.bf16x2.f32 %0, %1, %2;" : "=r"(r) : "f"(hi), "f"(lo));
    return r;
}
__device__ __forceinline__ void ldsm4(uint32_t* r, uint32_t addr) {
    asm volatile("ldmatrix.sync.aligned.m8n8.x4.shared.b16 {%0,%1,%2,%3}, [%4];"
                 : "=r"(r[0]), "=r"(r[1]), "=r"(r[2]), "=r"(r[3]) : "r"(addr));
}
__device__ __forceinline__ void mma16816(float* d, const uint32_t* a, const uint32_t* b) {
    asm volatile(
        "mma.sync.aligned.m16n8k16.row.col.f32.bf16.bf16.f32 "
        "{%0,%1,%2,%3}, {%4,%5,%6,%7}, {%8,%9}, {%0,%1,%2,%3};"
        : "+f"(d[0]), "+f"(d[1]), "+f"(d[2]), "+f"(d[3])
        : "r"(a[0]), "r"(a[1]), "r"(a[2]), "r"(a[3]), "r"(b[0]), "r"(b[1]));
}
__device__ __forceinline__ void cp_async16(uint32_t dst, const void* src) {
    asm volatile("cp.async.cg.shared.global [%0], [%1], 16;" :: "r"(dst), "l"(src));
}
#define CP_COMMIT() asm volatile("cp.async.commit_group;" ::: "memory")
#define CP_WAIT0()  asm volatile("cp.async.wait_group 0;" ::: "memory")

// ---------------------------------------------------------------------------
// Weight transpose + bf16 convert (tiny, once per launch)
// ---------------------------------------------------------------------------
__global__ void prep_weights(const float* __restrict__ aw1, const float* __restrict__ aw2,
                             const float* __restrict__ lw1, const float* __restrict__ lw2)
{
    int i = blockIdx.x * blockDim.x + threadIdx.x;
    if (i < H_ * ACT_) {
        int n = i / ACT_, k = i % ACT_;
        g_aw1t[i] = __float2bfloat16(aw1[k * H_ + n]);
    }
    int i2 = i - H_ * ACT_;
    if (i2 >= 0 && i2 < H_ * H_) {
        int n = i2 / H_, k = i2 % H_;
        g_aw2t[i2] = __float2bfloat16(aw2[k * H_ + n]);
    }
    int i3 = i2 - H_ * H_;
    if (i3 >= 0 && i3 < H_ * LATENT_) {
        int n = i3 / LATENT_, k = i3 % LATENT_;
        g_lw1t[i3] = __float2bfloat16(lw1[k * H_ + n]);
    }
    int i4 = i3 - H_ * H_;
    if (i4 >= 0 && i4 < H_ * H_) {
        int n = i4 / H_, k = i4 % H_;
        g_lw2t[i4] = __float2bfloat16(lw2[k * H_ + n]);
    }
}

// ---------------------------------------------------------------------------
// Fused 2-layer MLP body: 64-row x 128-col tile, 8 warps (2x4 grid, 32x32 each)
// ---------------------------------------------------------------------------
template <int KIN>
__device__ __forceinline__ void mlp_body(
    const float* __restrict__ X,
    const __nv_bfloat16* __restrict__ w1t, const __nv_bfloat16* __restrict__ w2t,
    const float* __restrict__ b1g, const float* __restrict__ b2g,
    __nv_bfloat16* __restrict__ out, int tile, char* smem)
{
    constexpr int S1 = KIN + 8;                 // halves
    constexpr int SH = H_ + 8;                  // halves
    constexpr int R1 = (S1 > SH ? 64 * S1 : 64 * SH) * 2;
    constexpr int R2 = (S1 > SH ? 128 * S1 : 128 * SH) * 2;

    char* r1 = smem;                            // Xs -> hidden -> out stage
    char* r2 = smem + R1;                       // W1T -> W2T
    float* b1s = (float*)(smem + R1 + R2);
    float* b2s = b1s + 128;
    const uint32_t sb1 = smem_u32(r1);
    const uint32_t sb2 = smem_u32(r2);

    const int tid  = threadIdx.x;
    const int wid  = tid >> 5;
    const int lane = tid & 31;
    const int rowBase = tile * 64;
    const int wr0 = (wid >> 2) * 32;            // warp row base (0/32)
    const int wc0 = (wid & 3) * 32;             // warp col base (0..96)

    const int a_row = (lane & 7) + ((lane >> 3) & 1) * 8;
    const int a_k   = (lane >> 4) * 8;
    const int b_n   = (lane & 7) + ((lane >> 4) & 1) * 8;
    const int b_k   = ((lane >> 3) & 1) * 8;

    if (tid < 128) { b1s[tid] = b1g[tid]; b2s[tid] = b2g[tid]; }

    // ---- async-stage W1T [128][KIN] bf16 (gmem is already bf16) ----
    {
        constexpr int NC = 128 * KIN / 8 / 256;
#pragma unroll
        for (int p = 0; p < NC; p++) {
            int idx = tid + p * 256;
            int r = idx / (KIN / 8), c = (idx % (KIN / 8)) * 8;
            cp_async16(sb2 + (uint32_t)(r * S1 + c) * 2, w1t + r * KIN + c);
        }
        CP_COMMIT();
    }
    // ---- stage X: batched LDG -> convert -> STS ----
    {
        constexpr int XV = 64 * KIN / 4 / 256;
        float4 xr[XV];
#pragma unroll
        for (int p = 0; p < XV; p++) {
            int idx = tid + p * 256;
            int r = idx / (KIN / 4), c = (idx % (KIN / 4)) * 4;
            xr[p] = *(const float4*)(X + (size_t)(rowBase + r) * KIN + c);
        }
#pragma unroll
        for (int p = 0; p < XV; p++) {
            int idx = tid + p * 256;
            int r = idx / (KIN / 4), c = (idx % (KIN / 4)) * 4;
            uint2 u;
            u.x = pack_bf16x2(san(xr[p].x), san(xr[p].y));
            u.y = pack_bf16x2(san(xr[p].z), san(xr[p].w));
            *(uint2*)(r1 + (r * S1 + c) * 2) = u;
        }
    }
    CP_WAIT0();
    __syncthreads();

    float acc[2][4][4];
#pragma unroll
    for (int mi = 0; mi < 2; mi++)
#pragma unroll
        for (int ni = 0; ni < 4; ni++)
#pragma unroll
            for (int q = 0; q < 4; q++) acc[mi][ni][q] = 0.0f;

    // ---- layer 1 mma ----
    {
        uint32_t aaddr[2], baddr[2];
#pragma unroll
        for (int mi = 0; mi < 2; mi++)
            aaddr[mi] = sb1 + (uint32_t)((wr0 + mi * 16 + a_row) * S1 + a_k) * 2;
#pragma unroll
        for (int bi = 0; bi < 2; bi++)
            baddr[bi] = sb2 + (uint32_t)((wc0 + bi * 16 + b_n) * S1 + b_k) * 2;
#pragma unroll
        for (int ks = 0; ks < KIN / 16; ks++) {
            uint32_t a[2][4], b[4][2];
#pragma unroll
            for (int mi = 0; mi < 2; mi++) ldsm4(a[mi], aaddr[mi] + ks * 32);
#pragma unroll
            for (int bi = 0; bi < 2; bi++) {
                uint32_t t[4];
                ldsm4(t, baddr[bi] + ks * 32);
                b[bi * 2][0] = t[0]; b[bi * 2][1] = t[1];
                b[bi * 2 + 1][0] = t[2]; b[bi * 2 + 1][1] = t[3];
            }
#pragma unroll
            for (int mi = 0; mi < 2; mi++)
#pragma unroll
                for (int ni = 0; ni < 4; ni++) mma16816(acc[mi][ni], a[mi], b[ni]);
        }
    }
    __syncthreads();   // layer-1 reads of r1/r2 complete

    // ---- async-stage W2T (hidden behind epilogue 1) + hidden = relu(acc+b1) ----
    {
        constexpr int NC2 = 128 * H_ / 8 / 256;   // 8
#pragma unroll
        for (int p = 0; p < NC2; p++) {
            int idx = tid + p * 256;
            int r = idx / (H_ / 8), c = (idx % (H_ / 8)) * 8;
            cp_async16(sb2 + (uint32_t)(r * SH + c) * 2, w2t + r * H_ + c);
        }
        CP_COMMIT();

        const int tr = lane >> 2, tc = (lane & 3) * 2;
#pragma unroll
        for (int mi = 0; mi < 2; mi++)
#pragma unroll
            for (int ni = 0; ni < 4; ni++) {
                int col = wc0 + ni * 8 + tc;
                float bb0 = b1s[col], bb1 = b1s[col + 1];
                int row0 = wr0 + mi * 16 + tr;
                *(uint32_t*)(r1 + (row0 * SH + col) * 2) =
                    pack_bf16x2(fmaxf(acc[mi][ni][0] + bb0, 0.0f),
                                fmaxf(acc[mi][ni][1] + bb1, 0.0f));
                *(uint32_t*)(r1 + ((row0 + 8) * SH + col) * 2) =
                    pack_bf16x2(fmaxf(acc[mi][ni][2] + bb0, 0.0f),
                                fmaxf(acc[mi][ni][3] + bb1, 0.0f));
            }
        CP_WAIT0();
    }
    __syncthreads();

    // ---- layer 2 mma ----
#pragma unroll
    for (int mi = 0; mi < 2; mi++)
#pragma unroll
        for (int ni = 0; ni < 4; ni++)
#pragma unroll
            for (int q = 0; q < 4; q++) acc[mi][ni][q] = 0.0f;
    {
        uint32_t aaddr[2], baddr[2];
#pragma unroll
        for (int mi = 0; mi < 2; mi++)
            aaddr[mi] = sb1 + (uint32_t)((wr0 + mi * 16 + a_row) * SH + a_k) * 2;
#pragma unroll
        for (int bi = 0; bi < 2; bi++)
            baddr[bi] = sb2 + (uint32_t)((wc0 + bi * 16 + b_n) * SH + b_k) * 2;
#pragma unroll
        for (int ks = 0; ks < H_ / 16; ks++) {
            uint32_t a[2][4], b[4][2];
#pragma unroll
            for (int mi = 0; mi < 2; mi++) ldsm4(a[mi], aaddr[mi] + ks * 32);
#pragma unroll
            for (int bi = 0; bi < 2; bi++) {
                uint32_t t[4];
                ldsm4(t, baddr[bi] + ks * 32);
                b[bi * 2][0] = t[0]; b[bi * 2][1] = t[1];
                b[bi * 2 + 1][0] = t[2]; b[bi * 2 + 1][1] = t[3];
            }
#pragma unroll
            for (int mi = 0; mi < 2; mi++)
#pragma unroll
                for (int ni = 0; ni < 4; ni++) mma16816(acc[mi][ni], a[mi], b[ni]);
        }
    }
    __syncthreads();   // layer-2 reads complete

    // ---- epilogue 2: san(acc + b2) -> staged bf16 [64][SH] -> coalesced gmem ----
    {
        const int tr = lane >> 2, tc = (lane & 3) * 2;
#pragma unroll
        for (int mi = 0; mi < 2; mi++)
#pragma unroll
            for (int ni = 0; ni < 4; ni++) {
                int col = wc0 + ni * 8 + tc;
                float bb0 = b2s[col], bb1 = b2s[col + 1];
                int row0 = wr0 + mi * 16 + tr;
                *(uint32_t*)(r1 + (row0 * SH + col) * 2) =
                    pack_bf16x2(san(acc[mi][ni][0] + bb0), san(acc[mi][ni][1] + bb1));
                *(uint32_t*)(r1 + ((row0 + 8) * SH + col) * 2) =
                    pack_bf16x2(san(acc[mi][ni][2] + bb0), san(acc[mi][ni][3] + bb1));
            }
    }
    __syncthreads();
    {
        uint4* dst = (uint4*)(out + (size_t)rowBase * H_);
        const uint4* src = (const uint4*)r1;
        for (int i = tid; i < 1024; i += 256) {     // 64 rows x 16 uint4
            int r = i >> 4, c = i & 15;
            dst[i] = src[r * (SH / 8) + c];         // SH/8 = 17
        }
    }
}

// One launch for all three MLPs. queue first (1024), latent (256), action (256).
__global__ __launch_bounds__(256, 2) void fused_mlp(
    const float* __restrict__ action, const float* __restrict__ latent,
    const float* __restrict__ queue,
    const float* __restrict__ ab1, const float* __restrict__ ab2,
    const float* __restrict__ lb1, const float* __restrict__ lb2)
{
    extern __shared__ __align__(16) char smem[];
    int bid = blockIdx.x;
    if (bid < 1024) {
        mlp_body<LATENT_>(queue, g_lw1t, g_lw2t, lb1, lb2, g_negemb, bid, smem);
    } else if (bid < 1280) {
        mlp_body<LATENT_>(latent, g_lw1t, g_lw2t, lb1, lb2, g_emb_l, bid - 1024, smem);
    } else {
        mlp_body<ACT_>(action, g_aw1t, g_aw2t, ab1, ab2, g_emb_a, bid - 1280, smem);
    }
}

// ---------------------------------------------------------------------------
// Loss: one warp per sample. bf16 embeddings (4 per lane -> 128 dims).
// ---------------------------------------------------------------------------
__device__ __forceinline__ float2 bf2(uint32_t u) {
    return __bfloat1622float2(*reinterpret_cast<__nv_bfloat162*>(&u));
}

__global__ __launch_bounds__(256) void loss_kernel(
    const int* __restrict__ neg_idx,
    const float* __restrict__ temp_ptr,
    float* __restrict__ out)
{
    const int warp = threadIdx.x >> 5;
    const int lane = threadIdx.x & 31;
    const int b = blockIdx.x * 8 + warp;

    float t = *temp_ptr;
    if (!isfinite(t)) t = 0.1f;
    t = fminf(fmaxf(t, 0.01f), 10.0f);
    const float invt = 1.0f / t;

    uint2 au = *(const uint2*)(g_emb_a + (size_t)b * H_ + lane * 4);
    float2 a01 = bf2(au.x), a23 = bf2(au.y);
    const int my_idx = neg_idx[b * K_ + lane];

    uint2 lu = *(const uint2*)(g_emb_l + (size_t)b * H_ + lane * 4);
    float2 l01 = bf2(lu.x), l23 = bf2(lu.y);
    float s = a01.x * l01.x + a01.y * l01.y + a23.x * l23.x + a23.y * l23.y;
#pragma unroll
    for (int o = 16; o > 0; o >>= 1) s += __shfl_xor_sync(0xffffffffu, s, o);
    float pos = s;

    float myneg = 0.0f;
    for (int k = 0; k < K_; k++) {
        int row = __shfl_sync(0xffffffffu, my_idx, k);
        uint2 nu = *(const uint2*)(g_negemb + (size_t)row * H_ + lane * 4);
        float2 n01 = bf2(nu.x), n23 = bf2(nu.y);
        float d = a01.x * n01.x + a01.y * n01.y + a23.x * n23.x + a23.y * n23.y;
#pragma unroll
        for (int o = 16; o > 0; o >>= 1) d += __shfl_xor_sync(0xffffffffu, d, o);
        if (lane == k) myneg = d;
    }

    pos *= invt;
    if (!isfinite(pos)) pos = 0.0f;
    pos = fminf(fmaxf(pos, -20.0f), 20.0f);
    myneg *= invt;
    if (!isfinite(myneg)) myneg = 0.0f;
    myneg = fminf(fmaxf(myneg, -20.0f), 20.0f);

    float m = myneg;
#pragma unroll
    for (int o = 16; o > 0; o >>= 1) m = fmaxf(m, __shfl_xor_sync(0xffffffffu, m, o));
    m = fmaxf(m, pos);

    float se = expf(myneg - m);
    float sl = myneg;
#pragma unroll
    for (int o = 16; o > 0; o >>= 1) {
        se += __shfl_xor_sync(0xffffffffu, se, o);
        sl += __shfl_xor_sync(0xffffffffu, sl, o);
    }
    se += expf(pos - m);
    sl += pos;

    float lse = m + logf(se);
    float logp0 = pos - lse;
    float meanlogp = sl * (1.0f / 33.0f) - lse;

    float loss = -(1.0f - EPS_) * logp0 - EPS_ * meanlogp;
    if (!isfinite(loss)) loss = 0.0f;
    loss = fminf(fmaxf(loss, -10.0f), 10.0f);

    if (lane == 0) out[b] = -loss;
}

// ---------------------------------------------------------------------------
extern "C" void kernel_launch(void* const* d_in, const int* in_sizes, int n_in,
                              void* d_out, int out_size)
{
    const float* action  = (const float*)d_in[0];
    const float* latent  = (const float*)d_in[1];
    const float* queue   = (const float*)d_in[2];
    const int*   neg_idx = (const int*)  d_in[3];
    const float* a_w1 = (const float*)d_in[4];
    const float* a_b1 = (const float*)d_in[5];
    const float* a_w2 = (const float*)d_in[6];
    const float* a_b2 = (const float*)d_in[7];
    const float* l_w1 = (const float*)d_in[8];
    const float* l_b1 = (const float*)d_in[9];
    const float* l_w2 = (const float*)d_in[10];
    const float* l_b2 = (const float*)d_in[11];
    const float* temp = (const float*)d_in[12];
    float* out = (float*)d_out;

    // smem for KIN=256 branch: R1 = 64*264*2 = 33792, R2 = 128*264*2 = 67584, bias 1024
    const int SMEM = 33792 + 67584 + 1024;      // 102400 -> 2 CTAs/SM

    cudaFuncSetAttribute((const void*)fused_mlp,
                         cudaFuncAttributeMaxDynamicSharedMemorySize, SMEM);

    prep_weights<<<(H_ * ACT_ + H_ * H_ + H_ * LATENT_ + H_ * H_ + 255) / 256, 256>>>(
        a_w1, a_w2, l_w1, l_w2);

    fused_mlp<<<1536, 256, SMEM>>>(action, latent, queue, a_b1, a_b2, l_b1, l_b2);

    loss_kernel<<<B_ / 8, 256>>>(neg_idx, temp, out);
}